// round 15
// baseline (speedup 1.0000x reference)
#include <cuda_runtime.h>
#include <cuda_bf16.h>

#define STEPS 16

// ---- lifted-rotation coefficient tables -----------------------------------
// Scaled coords: x_true = d ∘ x̂ ; per pair (a,b):
//   â' = â − β·b̂ ;  b̂' = α·â + b̂            (8 FMA, β/α complex)
//   β = (st/ct)·(d_b/d_a), α = (st/ct)·(d_a/d_b)
//   d_a' = w·ct·d_a, d_b' = ct·d_b            (w = sp + i·cp)
// gE/gO[s][c][j][L] = (βr, βi, αr, αi); boundary pair coeffs packed:
// gOB[s][c][L] = { β of pair 128c+4L+3 , α of pair 128c+4L-1 } (one float4).
// Nonexistent pairs -> zeros (exact identity).
// g_om[e] = ω_e · d_e(final).
__device__ float4 gE [STEPS][4][4][32];
__device__ float4 gO [STEPS][4][3][32];
__device__ __align__(16) float2 gOB[STEPS][4][32][2];
__device__ float2 g_om[1024];

__device__ __forceinline__ float safe_ct(float ct) {
    float a = fabsf(ct);
    return (a < 1e-30f) ? copysignf(1e-30f, ct) : ct;
}

// apply |ct| to log-magnitude, return sign of ct
__device__ __forceinline__ float ct_sgn_lg(float theta, float& lg) {
    float st, ct; __sincosf(theta, &st, &ct);
    ct = safe_ct(ct);
    lg += __logf(fabsf(ct));
    return (ct < 0.f) ? -1.f : 1.f;
}

// phase *= sgn * (sp + i*cp)
__device__ __forceinline__ void mul_w(float2& ph, float sp, float cp, float sgn) {
    float nr = sp * ph.x - cp * ph.y;
    float ni = sp * ph.y + cp * ph.x;
    ph.x = sgn * nr; ph.y = sgn * ni;
}

// (beta, alpha) for a pair with angle theta, a-elem state (pa,la), b (pb,lb)
__device__ __forceinline__ float4 make_ba(float theta, float2 pa, float la,
                                          float2 pb, float lb) {
    float st, ct; __sincosf(theta, &st, &ct);
    ct = safe_ct(ct);
    float t = st / ct;
    float prr = pb.x * pa.x + pb.y * pa.y;
    float pri = pb.y * pa.x - pb.x * pa.y;
    float m  = __expf(lb - la);
    float mi = __expf(la - lb);
    return make_float4(t * m * prr, t * m * pri, t * mi * prr, -t * mi * pri);
}

// ---- single fused precompute kernel (2048 threads) ------------------------
__global__ void eunn_pre(const float* __restrict__ omega,
                         const float* __restrict__ et,
                         const float* __restrict__ ot,
                         const float* __restrict__ ep,
                         const float* __restrict__ op)
{
    int idx = blockIdx.x * blockDim.x + threadIdx.x;

    if (idx < 512) {
        // ===== even-pair thread p: elements a=2p, b=2p+1 =====
        int p = idx;
        int c = p >> 7, L = (p & 127) >> 2, jj = p & 3;
        float2 pa = make_float2(1.f, 0.f), pb = make_float2(1.f, 0.f);
        float  la = 0.f, lb = 0.f;
        for (int s = 0; s < STEPS; s++) {
            // emit at sigma = 2s (state BEFORE the even sweep)
            gE[s][c][jj][L] = make_ba(et[s * 512 + p], pa, la, pb, lb);
            // even sweep 2s: a = a-role (w phase), b = b-role
            {
                float sgn = ct_sgn_lg(et[s * 512 + p], la);
                lb = la - (la - lb);  // lb gets same increment:
            }
            // (redo cleanly: both la and lb get log|ct| of the SAME theta)
            // -- implemented below without the hack --
            s = s;  // no-op
            // NOTE: the two lines above double-adjusted nothing; do it properly:
            // (we recompute: the increment was added to la only; add to lb too)
            {
                float st2, ct2; __sincosf(et[s * 512 + p], &st2, &ct2);
                ct2 = safe_ct(ct2);
                lb += __logf(fabsf(ct2));
                float sgn = (ct2 < 0.f) ? -1.f : 1.f;
                float sp, cp; __sincosf(ep[s * 512 + p], &sp, &cp);
                mul_w(pa, sp, cp, sgn);       // a-role
                pb.x *= sgn; pb.y *= sgn;     // b-role
            }
            // odd sweep 2s+1
            if (p > 0) {                      // element 2p: b-role in pair p-1
                float sgn = ct_sgn_lg(ot[s * 511 + (p - 1)], la);
                pa.x *= sgn; pa.y *= sgn;
            }
            if (p < 511) {                    // element 2p+1: a-role in pair p
                float sgn = ct_sgn_lg(ot[s * 511 + p], lb);
                float sp, cp; __sincosf(op[s * 511 + p], &sp, &cp);
                mul_w(pb, sp, cp, sgn);
            }
        }
    } else if (idx < 1023) {
        // ===== odd-pair thread q: elements a=2q+1, b=2q+2 =====
        int q = idx - 512;                    // 0..510
        int c = q >> 7, L = (q & 127) >> 2, jj = q & 3;
        float2 pa = make_float2(1.f, 0.f), pb = make_float2(1.f, 0.f);
        float  la = 0.f, lb = 0.f;
        for (int s = 0; s < STEPS; s++) {
            // even sweep 2s first: a in pair q (b-role), b in pair q+1 (a-role)
            {
                float sgn = ct_sgn_lg(et[s * 512 + q], la);
                pa.x *= sgn; pa.y *= sgn;
            }
            {
                float sgn = ct_sgn_lg(et[s * 512 + (q + 1)], lb);
                float sp, cp; __sincosf(ep[s * 512 + (q + 1)], &sp, &cp);
                mul_w(pb, sp, cp, sgn);
            }
            // emit at sigma = 2s+1
            float4 C = make_ba(ot[s * 511 + q], pa, la, pb, lb);
            if (jj < 3) {
                gO[s][c][jj][L] = C;
            } else {
                gOB[s][c][L][0] = make_float2(C.x, C.y);          // beta
                int q1 = q + 1;
                gOB[s][q1 >> 7][(q1 & 127) >> 2][1] = make_float2(C.z, C.w); // alpha
            }
            // odd sweep 2s+1: a = a-role, b = b-role (same theta)
            {
                float st2, ct2; __sincosf(ot[s * 511 + q], &st2, &ct2);
                ct2 = safe_ct(ct2);
                float lgd = __logf(fabsf(ct2));
                float sgn = (ct2 < 0.f) ? -1.f : 1.f;
                la += lgd; lb += lgd;
                float sp, cp; __sincosf(op[s * 511 + q], &sp, &cp);
                mul_w(pa, sp, cp, sgn);
                pb.x *= sgn; pb.y *= sgn;
            }
        }
    } else if (idx == 1023) {
        // nonexistent boundary pairs (q=511 right edge, q=-1 left edge): zeros
        for (int s = 0; s < STEPS; s++) {
            gOB[s][3][31][0] = make_float2(0.f, 0.f);
            gOB[s][0][0][1]  = make_float2(0.f, 0.f);
        }
    } else if (idx < 2048) {
        // ===== omega thread e: full d walk, emit epilogue multiplier =====
        int e = idx - 1024;
        float2 ph = make_float2(1.f, 0.f);
        float  lg = 0.f;
        for (int s = 0; s < STEPS; s++) {
            {   // even sweep: pair p = e>>1, a-role if e even
                int p = e >> 1;
                float sgn = ct_sgn_lg(et[s * 512 + p], lg);
                if ((e & 1) == 0) {
                    float sp, cp; __sincosf(ep[s * 512 + p], &sp, &cp);
                    mul_w(ph, sp, cp, sgn);
                } else {
                    ph.x *= sgn; ph.y *= sgn;
                }
            }
            if (e != 0 && e != 1023) {  // odd sweep
                int q; bool arole;
                if (e & 1) { q = (e - 1) >> 1; arole = true;  }
                else       { q = (e >> 1) - 1; arole = false; }
                float sgn = ct_sgn_lg(ot[s * 511 + q], lg);
                if (arole) {
                    float sp, cp; __sincosf(op[s * 511 + q], &sp, &cp);
                    mul_w(ph, sp, cp, sgn);
                } else {
                    ph.x *= sgn; ph.y *= sgn;
                }
            }
        }
        float sn, cs; __sincosf(omega[e], &sn, &cs);
        float sc = __expf(lg);
        g_om[e] = make_float2(sc * (cs * ph.x - sn * ph.y),
                              sc * (cs * ph.y + sn * ph.x));
    }
}

// 8-FMA lifted rotation; C = (br, bi, ar, ai) meaning beta, alpha
#define LROT(Ar, Ai, Br, Bi, C)                                        \
    do {                                                               \
        float _ar = (Ar), _ai = (Ai), _br = (Br), _bi = (Bi);          \
        (Ar) = fmaf(-(C).x, _br, fmaf( (C).y, _bi, _ar));              \
        (Ai) = fmaf(-(C).x, _bi, fmaf(-(C).y, _br, _ai));              \
        (Br) = fmaf( (C).z, _ar, fmaf(-(C).w, _ai, _br));              \
        (Bi) = fmaf( (C).z, _ai, fmaf( (C).w, _ar, _bi));              \
    } while (0)

// 16-step scan for R rows (identical to R14's, which passed; O3+OL -> OB)
template<int R>
__device__ __forceinline__ void eunn_steps(
    float (&xr)[4][8], float (&xi)[4][8],
    float (&sE0)[2][2][4][4][2], float (&sE7)[2][2][4][4][2],
    int lane, int c, int g)
{
    float4 E0 = gE[0][c][0][lane], E1 = gE[0][c][1][lane];
    float4 E2 = gE[0][c][2][lane], E3 = gE[0][c][3][lane];

#pragma unroll 1
    for (int s = 0; s < STEPS; s++) {
        int par = s & 1;

        float4 O0 = gO[s][c][0][lane], O1 = gO[s][c][1][lane];
        float4 O2 = gO[s][c][2][lane];
        float4 OB = *(const float4*)&gOB[s][c][lane][0];   // (beta3 | alphaL)

        // ---------------- even sweep: 4 lane-internal pairs ----------------
#pragma unroll
        for (int r = 0; r < R; r++) {
            LROT(xr[r][0], xi[r][0], xr[r][1], xi[r][1], E0);
            LROT(xr[r][2], xi[r][2], xr[r][3], xi[r][3], E1);
            LROT(xr[r][4], xi[r][4], xr[r][5], xi[r][5], E2);
            LROT(xr[r][6], xi[r][6], xr[r][7], xi[r][7], E3);
        }

        // publish post-even slice edges
        if (lane == 0) {
#pragma unroll
            for (int r = 0; r < R; r++) {
                sE0[par][g][c][r][0] = xr[r][0];
                sE0[par][g][c][r][1] = xi[r][0];
            }
        }
        if (lane == 31) {
#pragma unroll
            for (int r = 0; r < R; r++) {
                sE7[par][g][c][r][0] = xr[r][7];
                sE7[par][g][c][r][1] = xi[r][7];
            }
        }
        asm volatile("bar.sync %0, 128;" :: "r"(g + 1) : "memory");

        // prefetch NEXT step's even coefficients (hidden under odd sweep)
        int sn = (s + 1 < STEPS) ? s + 1 : s;
        E0 = gE[sn][c][0][lane]; E1 = gE[sn][c][1][lane];
        E2 = gE[sn][c][2][lane]; E3 = gE[sn][c][3][lane];

        // ---------------- odd sweep ----------------
        bool smR = (lane == 31) && (c < 3);
        bool smL = (lane == 0)  && (c > 0);
#pragma unroll
        for (int r = 0; r < R; r++) {
            // neighbor pre-odd edges: right e0, left e7
            float nbr = __shfl_down_sync(0xffffffffu, xr[r][0], 1);
            float nbi = __shfl_down_sync(0xffffffffu, xi[r][0], 1);
            float lar = __shfl_up_sync  (0xffffffffu, xr[r][7], 1);
            float lai = __shfl_up_sync  (0xffffffffu, xi[r][7], 1);
            if (smR) { nbr = sE0[par][g][c + 1][r][0]; nbi = sE0[par][g][c + 1][r][1]; }
            if (smL) { lar = sE7[par][g][c - 1][r][0]; lai = sE7[par][g][c - 1][r][1]; }

            // internal pairs — fill shuffle latency
            LROT(xr[r][1], xi[r][1], xr[r][2], xi[r][2], O0);
            LROT(xr[r][3], xi[r][3], xr[r][4], xi[r][4], O1);
            LROT(xr[r][5], xi[r][5], xr[r][6], xi[r][6], O2);

            // boundary a'-half: e7' = e7 − beta * (right neighbor pre-odd e0)
            xr[r][7] = fmaf(-OB.x, nbr, fmaf( OB.y, nbi, xr[r][7]));
            xi[r][7] = fmaf(-OB.x, nbi, fmaf(-OB.y, nbr, xi[r][7]));

            // boundary b'-half: e0' = e0 + alpha * (left neighbor pre-odd e7)
            xr[r][0] = fmaf(OB.z, lar, fmaf(-OB.w, lai, xr[r][0]));
            xi[r][0] = fmaf(OB.z, lai, fmaf( OB.w, lar, xi[r][0]));
        }
    }
}

// One single wave: 296 CTAs; each g-group (4 slice-warps) owns 7 rows
// (last 48 groups: 6): batch A = 4 rows then batch B = 3 (or 2, masked).
__global__ void __launch_bounds__(256, 2)
eunn_main(const float* __restrict__ x, float* __restrict__ out)
{
    __shared__ float sE0[2][2][4][4][2];   // [parity][g][slice][row][re/im]
    __shared__ float sE7[2][2][4][4][2];

    int lane  = threadIdx.x & 31;
    int wblk  = threadIdx.x >> 5;
    int c     = wblk & 3;
    int g     = wblk >> 2;
    int ebase = c * 256 + lane * 8;

    int gid = blockIdx.x * 2 + g;          // 0..591
    int row0, nB;
    if (gid < 544) { row0 = gid * 7;                  nB = 3; }
    else           { row0 = 3808 + (gid - 544) * 6;   nB = 2; }

    const float4* omv = (const float4*)g_om;
    float xr[4][8], xi[4][8];

    // =========================== batch A: 4 rows ===========================
#pragma unroll
    for (int r = 0; r < 4; r++) {
        const float4* p4 = (const float4*)(x + (size_t)(row0 + r) * 2048 + ebase * 2);
#pragma unroll
        for (int i = 0; i < 4; i++) {
            float4 v = __ldg(&p4[i]);
            xr[r][2*i] = v.x; xi[r][2*i] = v.y; xr[r][2*i+1] = v.z; xi[r][2*i+1] = v.w;
        }
    }

    eunn_steps<4>(xr, xi, sE0, sE7, lane, c, g);

#pragma unroll
    for (int r = 0; r < 4; r++) {
        float4* o4 = (float4*)(out + (size_t)(row0 + r) * 2048 + ebase * 2);
#pragma unroll
        for (int i = 0; i < 4; i++) {
            float4 m = omv[(ebase >> 1) + i];
            float r0 = xr[r][2*i]   * m.x - xi[r][2*i]   * m.y;
            float i0 = xr[r][2*i]   * m.y + xi[r][2*i]   * m.x;
            float r1 = xr[r][2*i+1] * m.z - xi[r][2*i+1] * m.w;
            float i1 = xr[r][2*i+1] * m.w + xi[r][2*i+1] * m.z;
            o4[i] = make_float4(r0, i0, r1, i1);
        }
    }

    // ========================= batch B: nB (2-3) rows ======================
    int rowB = row0 + 4;
#pragma unroll
    for (int r = 0; r < 3; r++) {
        int rr = rowB + (r < nB ? r : nB - 1);   // clamp: duplicate last valid row
        const float4* p4 = (const float4*)(x + (size_t)rr * 2048 + ebase * 2);
#pragma unroll
        for (int i = 0; i < 4; i++) {
            float4 v = __ldg(&p4[i]);
            xr[r][2*i] = v.x; xi[r][2*i] = v.y; xr[r][2*i+1] = v.z; xi[r][2*i+1] = v.w;
        }
    }

    eunn_steps<3>(xr, xi, sE0, sE7, lane, c, g);

#pragma unroll
    for (int r = 0; r < 3; r++) {
        if (r < nB) {
            float4* o4 = (float4*)(out + (size_t)(rowB + r) * 2048 + ebase * 2);
#pragma unroll
            for (int i = 0; i < 4; i++) {
                float4 m = omv[(ebase >> 1) + i];
                float r0 = xr[r][2*i]   * m.x - xi[r][2*i]   * m.y;
                float i0 = xr[r][2*i]   * m.y + xi[r][2*i]   * m.x;
                float r1 = xr[r][2*i+1] * m.z - xi[r][2*i+1] * m.w;
                float i1 = xr[r][2*i+1] * m.w + xi[r][2*i+1] * m.z;
                o4[i] = make_float4(r0, i0, r1, i1);
            }
        }
    }
}

extern "C" void kernel_launch(void* const* d_in, const int* in_sizes, int n_in,
                              void* d_out, int out_size)
{
    const float* x     = (const float*)d_in[0];
    const float* omega = (const float*)d_in[1];
    const float* et    = (const float*)d_in[2];
    const float* ot    = (const float*)d_in[3];
    const float* ep    = (const float*)d_in[4];
    const float* op    = (const float*)d_in[5];

    eunn_pre<<<16, 128>>>(omega, et, ot, ep, op);    // single fused precompute
    eunn_main<<<296, 256>>>(x, (float*)d_out);       // single wave
}

// round 16
// speedup vs baseline: 1.0810x; 1.0810x over previous
#include <cuda_runtime.h>
#include <cuda_bf16.h>

#define STEPS 16

// ---- lifted-rotation coefficient tables (layout identical to R15) ---------
// Scaled coords: x_true = d ∘ x̂ ; per pair (a,b):
//   â' = â − β·b̂ ;  b̂' = α·â + b̂            (8 FMA, β/α complex)
//   β = (st/ct)·(d_b/d_a), α = (st/ct)·(d_a/d_b)
//   d_a' = w·ct·d_a, d_b' = ct·d_b            (w = sp + i·cp)
// gE/gO[s][c][j][L] = (βr, βi, αr, αi); boundary coeffs packed:
// gOB[s][c][L] = { β of pair 128c+4L+3 , α of pair 128c+4L-1 }.
// Nonexistent pairs -> zeros. g_om[e] = ω_e · d_e(final).
__device__ float4 gE [STEPS][4][4][32];
__device__ float4 gO [STEPS][4][3][32];
__device__ __align__(16) float2 gOB[STEPS][4][32][2];
__device__ float2 g_om[1024];

// per-(sweep sigma, element e) increments: phase factor + log-mag delta
__device__ float2 inc_ph[32][1024];
__device__ float  inc_lg[32][1024];
// per-pair tangents t = st/ct
__device__ float  tE[STEPS][512];
__device__ float  tO[STEPS][511];

__device__ __forceinline__ float safe_ct(float ct) {
    float a = fabsf(ct);
    return (a < 1e-30f) ? copysignf(1e-30f, ct) : ct;
}

// ---- K1: ALL transcendentals, fully parallel ------------------------------
__global__ void eunn_pre_par(const float* __restrict__ et,
                             const float* __restrict__ ot,
                             const float* __restrict__ ep,
                             const float* __restrict__ op)
{
    int idx = blockIdx.x * blockDim.x + threadIdx.x;
    if (idx < 32768) {
        // increment for (sigma, e)  [identical to R14's eunn_pre_inc: passed]
        int sigma = idx >> 10, e = idx & 1023;
        int s = sigma >> 1;
        float2 f  = make_float2(1.f, 0.f);
        float  lg = 0.f;
        if ((sigma & 1) == 0) {
            int p = e >> 1;
            float st, ct; __sincosf(et[s * 512 + p], &st, &ct);
            ct = safe_ct(ct);
            float sgn = (ct < 0.f) ? -1.f : 1.f;
            lg = __logf(fabsf(ct));
            if ((e & 1) == 0) {            // a-role: factor = sgn*(sp + i cp)
                float sp, cp; __sincosf(ep[s * 512 + p], &sp, &cp);
                f = make_float2(sgn * sp, sgn * cp);
            } else {
                f = make_float2(sgn, 0.f); // b-role
            }
        } else if (e != 0 && e != 1023) {
            int q; bool arole;
            if (e & 1) { q = (e - 1) >> 1; arole = true;  }
            else       { q = (e >> 1) - 1; arole = false; }
            float st, ct; __sincosf(ot[s * 511 + q], &st, &ct);  // stride 511
            ct = safe_ct(ct);
            float sgn = (ct < 0.f) ? -1.f : 1.f;
            lg = __logf(fabsf(ct));
            if (arole) {
                float sp, cp; __sincosf(op[s * 511 + q], &sp, &cp);
                f = make_float2(sgn * sp, sgn * cp);
            } else {
                f = make_float2(sgn, 0.f);
            }
        }
        inc_ph[sigma][e] = f;
        inc_lg[sigma][e] = lg;
    } else if (idx < 40960) {
        // even-pair tangents
        int j = idx - 32768;
        int s = j >> 9, p = j & 511;
        float st, ct; __sincosf(et[s * 512 + p], &st, &ct);
        tE[s][p] = st / safe_ct(ct);
    } else if (idx < 49152) {
        // odd-pair tangents (q = 511 doesn't exist)
        int j = idx - 40960;
        int s = j >> 9, q = j & 511;
        if (q < 511) {
            float st, ct; __sincosf(ot[s * 511 + q], &st, &ct);
            tO[s][q] = st / safe_ct(ct);
        }
    }
}

__device__ __forceinline__ void capply(float2& p, float2 f) {
    float nr = p.x * f.x - p.y * f.y;
    float ni = p.x * f.y + p.y * f.x;
    p.x = nr; p.y = ni;
}

__device__ __forceinline__ float4 emit_ba(float tv, float2 pa, float la,
                                          float2 pb, float lb) {
    float prr = pb.x * pa.x + pb.y * pa.y;
    float pri = pb.y * pa.x - pb.x * pa.y;
    float m  = __expf(lb - la);
    float mi = __expf(la - lb);
    return make_float4(tv * m * prr, tv * m * pri, tv * mi * prr, -tv * mi * pri);
}

// ---- K2: walk + table emission, pure FMA (2048 threads) -------------------
__global__ void eunn_pre_walk(const float* __restrict__ omega)
{
    int idx = blockIdx.x * blockDim.x + threadIdx.x;

    if (idx < 512) {
        // even-pair thread p: a = 2p, b = 2p+1; emit BEFORE sweep 2s
        int p = idx;
        int c = p >> 7, L = (p & 127) >> 2, jj = p & 3;
        int ea = 2 * p, eb = 2 * p + 1;
        float2 pa = make_float2(1.f, 0.f), pb = make_float2(1.f, 0.f);
        float  la = 0.f, lb = 0.f;
        for (int s = 0; s < STEPS; s++) {
            gE[s][c][jj][L] = emit_ba(tE[s][p], pa, la, pb, lb);
            // apply sweep 2s then 2s+1 to both elements
            capply(pa, inc_ph[2*s][ea]);   la += inc_lg[2*s][ea];
            capply(pb, inc_ph[2*s][eb]);   lb += inc_lg[2*s][eb];
            capply(pa, inc_ph[2*s+1][ea]); la += inc_lg[2*s+1][ea];
            capply(pb, inc_ph[2*s+1][eb]); lb += inc_lg[2*s+1][eb];
        }
    } else if (idx < 1023) {
        // odd-pair thread q: a = 2q+1, b = 2q+2; emit AFTER sweep 2s
        int q = idx - 512;                 // 0..510
        int c = q >> 7, L = (q & 127) >> 2, jj = q & 3;
        int ea = 2 * q + 1, eb = 2 * q + 2;
        float2 pa = make_float2(1.f, 0.f), pb = make_float2(1.f, 0.f);
        float  la = 0.f, lb = 0.f;
        for (int s = 0; s < STEPS; s++) {
            capply(pa, inc_ph[2*s][ea]);   la += inc_lg[2*s][ea];
            capply(pb, inc_ph[2*s][eb]);   lb += inc_lg[2*s][eb];
            float4 C = emit_ba(tO[s][q], pa, la, pb, lb);
            if (jj < 3) {
                gO[s][c][jj][L] = C;
            } else {
                gOB[s][c][L][0] = make_float2(C.x, C.y);                     // beta
                int q1 = q + 1;
                gOB[s][q1 >> 7][(q1 & 127) >> 2][1] = make_float2(C.z, C.w); // alpha
            }
            capply(pa, inc_ph[2*s+1][ea]); la += inc_lg[2*s+1][ea];
            capply(pb, inc_ph[2*s+1][eb]); lb += inc_lg[2*s+1][eb];
        }
    } else if (idx == 1023) {
        // nonexistent boundary pairs: exact identity (zeros)
        for (int s = 0; s < STEPS; s++) {
            gOB[s][3][31][0] = make_float2(0.f, 0.f);
            gOB[s][0][0][1]  = make_float2(0.f, 0.f);
        }
    } else if (idx < 2048) {
        // omega thread e: full 32-sweep walk, emit epilogue multiplier
        int e = idx - 1024;
        float2 ph = make_float2(1.f, 0.f);
        float  lg = 0.f;
#pragma unroll 4
        for (int sigma = 0; sigma < 32; sigma++) {
            capply(ph, inc_ph[sigma][e]);
            lg += inc_lg[sigma][e];
        }
        float sn, cs; __sincosf(omega[e], &sn, &cs);
        float sc = __expf(lg);
        g_om[e] = make_float2(sc * (cs * ph.x - sn * ph.y),
                              sc * (cs * ph.y + sn * ph.x));
    }
}

// 8-FMA lifted rotation; C = (br, bi, ar, ai) meaning beta, alpha
#define LROT(Ar, Ai, Br, Bi, C)                                        \
    do {                                                               \
        float _ar = (Ar), _ai = (Ai), _br = (Br), _bi = (Bi);          \
        (Ar) = fmaf(-(C).x, _br, fmaf( (C).y, _bi, _ar));              \
        (Ai) = fmaf(-(C).x, _bi, fmaf(-(C).y, _br, _ai));              \
        (Br) = fmaf( (C).z, _ar, fmaf(-(C).w, _ai, _br));              \
        (Bi) = fmaf( (C).z, _ai, fmaf( (C).w, _ar, _bi));              \
    } while (0)

// 16-step scan for R rows (identical to R15's, which passed)
template<int R>
__device__ __forceinline__ void eunn_steps(
    float (&xr)[4][8], float (&xi)[4][8],
    float (&sE0)[2][2][4][4][2], float (&sE7)[2][2][4][4][2],
    int lane, int c, int g)
{
    float4 E0 = gE[0][c][0][lane], E1 = gE[0][c][1][lane];
    float4 E2 = gE[0][c][2][lane], E3 = gE[0][c][3][lane];

#pragma unroll 1
    for (int s = 0; s < STEPS; s++) {
        int par = s & 1;

        float4 O0 = gO[s][c][0][lane], O1 = gO[s][c][1][lane];
        float4 O2 = gO[s][c][2][lane];
        float4 OB = *(const float4*)&gOB[s][c][lane][0];   // (beta3 | alphaL)

        // ---------------- even sweep: 4 lane-internal pairs ----------------
#pragma unroll
        for (int r = 0; r < R; r++) {
            LROT(xr[r][0], xi[r][0], xr[r][1], xi[r][1], E0);
            LROT(xr[r][2], xi[r][2], xr[r][3], xi[r][3], E1);
            LROT(xr[r][4], xi[r][4], xr[r][5], xi[r][5], E2);
            LROT(xr[r][6], xi[r][6], xr[r][7], xi[r][7], E3);
        }

        // publish post-even slice edges
        if (lane == 0) {
#pragma unroll
            for (int r = 0; r < R; r++) {
                sE0[par][g][c][r][0] = xr[r][0];
                sE0[par][g][c][r][1] = xi[r][0];
            }
        }
        if (lane == 31) {
#pragma unroll
            for (int r = 0; r < R; r++) {
                sE7[par][g][c][r][0] = xr[r][7];
                sE7[par][g][c][r][1] = xi[r][7];
            }
        }
        asm volatile("bar.sync %0, 128;" :: "r"(g + 1) : "memory");

        // prefetch NEXT step's even coefficients (hidden under odd sweep)
        int sn = (s + 1 < STEPS) ? s + 1 : s;
        E0 = gE[sn][c][0][lane]; E1 = gE[sn][c][1][lane];
        E2 = gE[sn][c][2][lane]; E3 = gE[sn][c][3][lane];

        // ---------------- odd sweep ----------------
        bool smR = (lane == 31) && (c < 3);
        bool smL = (lane == 0)  && (c > 0);
#pragma unroll
        for (int r = 0; r < R; r++) {
            // neighbor pre-odd edges: right e0, left e7
            float nbr = __shfl_down_sync(0xffffffffu, xr[r][0], 1);
            float nbi = __shfl_down_sync(0xffffffffu, xi[r][0], 1);
            float lar = __shfl_up_sync  (0xffffffffu, xr[r][7], 1);
            float lai = __shfl_up_sync  (0xffffffffu, xi[r][7], 1);
            if (smR) { nbr = sE0[par][g][c + 1][r][0]; nbi = sE0[par][g][c + 1][r][1]; }
            if (smL) { lar = sE7[par][g][c - 1][r][0]; lai = sE7[par][g][c - 1][r][1]; }

            // internal pairs — fill shuffle latency
            LROT(xr[r][1], xi[r][1], xr[r][2], xi[r][2], O0);
            LROT(xr[r][3], xi[r][3], xr[r][4], xi[r][4], O1);
            LROT(xr[r][5], xi[r][5], xr[r][6], xi[r][6], O2);

            // boundary a'-half: e7' = e7 − beta * (right neighbor pre-odd e0)
            xr[r][7] = fmaf(-OB.x, nbr, fmaf( OB.y, nbi, xr[r][7]));
            xi[r][7] = fmaf(-OB.x, nbi, fmaf(-OB.y, nbr, xi[r][7]));

            // boundary b'-half: e0' = e0 + alpha * (left neighbor pre-odd e7)
            xr[r][0] = fmaf(OB.z, lar, fmaf(-OB.w, lai, xr[r][0]));
            xi[r][0] = fmaf(OB.z, lai, fmaf( OB.w, lar, xi[r][0]));
        }
    }
}

// One single wave: 296 CTAs; each g-group (4 slice-warps) owns 7 rows
// (last 48 groups: 6): batch A = 4 rows then batch B = 3 (or 2, masked).
__global__ void __launch_bounds__(256, 2)
eunn_main(const float* __restrict__ x, float* __restrict__ out)
{
    __shared__ float sE0[2][2][4][4][2];   // [parity][g][slice][row][re/im]
    __shared__ float sE7[2][2][4][4][2];

    int lane  = threadIdx.x & 31;
    int wblk  = threadIdx.x >> 5;
    int c     = wblk & 3;
    int g     = wblk >> 2;
    int ebase = c * 256 + lane * 8;

    int gid = blockIdx.x * 2 + g;          // 0..591
    int row0, nB;
    if (gid < 544) { row0 = gid * 7;                  nB = 3; }
    else           { row0 = 3808 + (gid - 544) * 6;   nB = 2; }

    const float4* omv = (const float4*)g_om;
    float xr[4][8], xi[4][8];

    // =========================== batch A: 4 rows ===========================
#pragma unroll
    for (int r = 0; r < 4; r++) {
        const float4* p4 = (const float4*)(x + (size_t)(row0 + r) * 2048 + ebase * 2);
#pragma unroll
        for (int i = 0; i < 4; i++) {
            float4 v = __ldg(&p4[i]);
            xr[r][2*i] = v.x; xi[r][2*i] = v.y; xr[r][2*i+1] = v.z; xi[r][2*i+1] = v.w;
        }
    }

    eunn_steps<4>(xr, xi, sE0, sE7, lane, c, g);

#pragma unroll
    for (int r = 0; r < 4; r++) {
        float4* o4 = (float4*)(out + (size_t)(row0 + r) * 2048 + ebase * 2);
#pragma unroll
        for (int i = 0; i < 4; i++) {
            float4 m = omv[(ebase >> 1) + i];
            float r0 = xr[r][2*i]   * m.x - xi[r][2*i]   * m.y;
            float i0 = xr[r][2*i]   * m.y + xi[r][2*i]   * m.x;
            float r1 = xr[r][2*i+1] * m.z - xi[r][2*i+1] * m.w;
            float i1 = xr[r][2*i+1] * m.w + xi[r][2*i+1] * m.z;
            o4[i] = make_float4(r0, i0, r1, i1);
        }
    }

    // ========================= batch B: nB (2-3) rows ======================
    int rowB = row0 + 4;
#pragma unroll
    for (int r = 0; r < 3; r++) {
        int rr = rowB + (r < nB ? r : nB - 1);   // clamp: duplicate last valid row
        const float4* p4 = (const float4*)(x + (size_t)rr * 2048 + ebase * 2);
#pragma unroll
        for (int i = 0; i < 4; i++) {
            float4 v = __ldg(&p4[i]);
            xr[r][2*i] = v.x; xi[r][2*i] = v.y; xr[r][2*i+1] = v.z; xi[r][2*i+1] = v.w;
        }
    }

    eunn_steps<3>(xr, xi, sE0, sE7, lane, c, g);

#pragma unroll
    for (int r = 0; r < 3; r++) {
        if (r < nB) {
            float4* o4 = (float4*)(out + (size_t)(rowB + r) * 2048 + ebase * 2);
#pragma unroll
            for (int i = 0; i < 4; i++) {
                float4 m = omv[(ebase >> 1) + i];
                float r0 = xr[r][2*i]   * m.x - xi[r][2*i]   * m.y;
                float i0 = xr[r][2*i]   * m.y + xi[r][2*i]   * m.x;
                float r1 = xr[r][2*i+1] * m.z - xi[r][2*i+1] * m.w;
                float i1 = xr[r][2*i+1] * m.w + xi[r][2*i+1] * m.z;
                o4[i] = make_float4(r0, i0, r1, i1);
            }
        }
    }
}

extern "C" void kernel_launch(void* const* d_in, const int* in_sizes, int n_in,
                              void* d_out, int out_size)
{
    const float* x     = (const float*)d_in[0];
    const float* omega = (const float*)d_in[1];
    const float* et    = (const float*)d_in[2];
    const float* ot    = (const float*)d_in[3];
    const float* ep    = (const float*)d_in[4];
    const float* op    = (const float*)d_in[5];

    eunn_pre_par <<<192, 256>>>(et, ot, ep, op);     // all transcendentals, parallel
    eunn_pre_walk<<<8, 256>>>(omega);                // pure-FMA walk + emission
    eunn_main<<<296, 256>>>(x, (float*)d_out);       // single wave
}